// round 1
// baseline (speedup 1.0000x reference)
#include <cuda_runtime.h>
#include <math.h>

#define B    8
#define NN   1024
#define CIN  256
#define COUT 256
#define RR   4
#define HH   4
#define ALPHA 0.2f

// -------- scratch (static __device__, per allocation rules) --------
__device__ float g_F[(size_t)RR * B * NN * COUT];         // [(r*B+b)*N+n][256]  (33.5 MB)
// per-node per-(r,h) scalars, layout [r][b][h][n] for coalesced j-staging
__device__ float g_E1 [RR * B * HH * NN];   // exp(lj)
__device__ float g_E2 [RR * B * HH * NN];   // exp(0.2*lj)
__device__ float g_T  [RR * B * HH * NN];   // exp(-li)   (regime threshold)
__device__ float g_A1p[RR * B * HH * NN];   // exp(li)
__device__ float g_A2p[RR * B * HH * NN];   // exp(0.2*li)
__device__ float g_A1 [RR * B * HH * NN];   // exp(li)/den
__device__ float g_A2 [RR * B * HH * NN];   // exp(0.2*li)/den
__device__ unsigned g_mask[B * NN * RR * (NN / 32)];      // [((b*N+i)*R+r)*32 + j/32]

#define LIDX(r, b, h, n) ((((r) * B + (b)) * HH + (h)) * NN + (n))

// -------- kernel 0: zero output --------
__global__ void k_zero(float* __restrict__ out, int nel) {
    int i = blockIdx.x * 256 + threadIdx.x;
    if (i < nel) out[i] = 0.f;
}

// -------- kernel 1: F_r = X @ W[r]  (128x128 tile, 8x8 per-thread) --------
__global__ __launch_bounds__(256) void k_gemm(const float* __restrict__ X,
                                              const float* __restrict__ W) {
    int r  = blockIdx.z;
    int m0 = blockIdx.y * 128;
    int d0 = blockIdx.x * 128;
    __shared__ float As[8][128];
    __shared__ float Bs[8][128];
    const float* Wr = W + (size_t)r * CIN * COUT;
    float acc[8][8];
#pragma unroll
    for (int i = 0; i < 8; i++)
#pragma unroll
        for (int j = 0; j < 8; j++) acc[i][j] = 0.f;

    int tid = threadIdx.x;
    int tx = tid & 15, ty = tid >> 4;

    for (int k0 = 0; k0 < CIN; k0 += 8) {
        {
            int row = tid >> 1;
            int kq  = (tid & 1) * 4;
            float4 va = *(const float4*)(X + (size_t)(m0 + row) * CIN + k0 + kq);
            As[kq + 0][row] = va.x; As[kq + 1][row] = va.y;
            As[kq + 2][row] = va.z; As[kq + 3][row] = va.w;
        }
        {
            int krow = tid >> 5;
            int dq   = (tid & 31) * 4;
            *(float4*)&Bs[krow][dq] =
                *(const float4*)(Wr + (size_t)(k0 + krow) * COUT + d0 + dq);
        }
        __syncthreads();
#pragma unroll
        for (int kk = 0; kk < 8; kk++) {
            float av[8], bv[8];
            *(float4*)&av[0] = *(float4*)&As[kk][ty * 8];
            *(float4*)&av[4] = *(float4*)&As[kk][ty * 8 + 4];
            *(float4*)&bv[0] = *(float4*)&Bs[kk][tx * 8];
            *(float4*)&bv[4] = *(float4*)&Bs[kk][tx * 8 + 4];
#pragma unroll
            for (int i = 0; i < 8; i++)
#pragma unroll
                for (int j = 0; j < 8; j++)
                    acc[i][j] = fmaf(av[i], bv[j], acc[i][j]);
        }
        __syncthreads();
    }
    float* Fo = g_F + (size_t)r * (B * NN) * COUT;
#pragma unroll
    for (int i = 0; i < 8; i++) {
        int m = m0 + ty * 8 + i;
#pragma unroll
        for (int jq = 0; jq < 8; jq += 4) {
            float4 v = make_float4(acc[i][jq], acc[i][jq + 1], acc[i][jq + 2], acc[i][jq + 3]);
            *(float4*)(Fo + (size_t)m * COUT + d0 + tx * 8 + jq) = v;
        }
    }
}

// -------- kernel 2: li/lj dots + exp factor tables --------
__global__ __launch_bounds__(256) void k_lvec(const float* __restrict__ a) {
    int warp = threadIdx.x >> 5, lane = threadIdx.x & 31;
    int rbn = blockIdx.x * 8 + warp;           // 0 .. R*B*N-1
    int r = rbn >> 13;                          // / (B*N)
    int bn = rbn & 8191;                        // b*N + n
    int b = bn >> 10, n = bn & 1023;
    const float* f = g_F + (size_t)rbn * COUT;
#pragma unroll
    for (int h = 0; h < HH; h++) {
        const float* ah = a + (r * HH + h) * 128;
        float f1 = f[h * 64 + lane];
        float f2 = f[h * 64 + 32 + lane];
        float li = f1 * ah[lane]      + f2 * ah[32 + lane];
        float lj = f1 * ah[64 + lane] + f2 * ah[96 + lane];
#pragma unroll
        for (int o = 16; o > 0; o >>= 1) {
            li += __shfl_xor_sync(~0u, li, o);
            lj += __shfl_xor_sync(~0u, lj, o);
        }
        if (lane == 0) {
            int idx = LIDX(r, b, h, n);
            g_E1[idx]  = expf(lj);
            g_E2[idx]  = expf(ALPHA * lj);
            g_T[idx]   = expf(-li);
            g_A1p[idx] = expf(li);
            g_A2p[idx] = expf(ALPHA * li);
        }
    }
}

// -------- kernel 3: softmax denominators + packed adjacency bits --------
// block = (b, 8 rows i); one warp per i; single pass over j (no max-sub needed)
#define JC 128
__global__ __launch_bounds__(256) void k_passA(const int* __restrict__ adj) {
    int b  = blockIdx.y;
    int i0 = blockIdx.x * 8;
    int warp = threadIdx.x >> 5, lane = threadIdx.x & 31;
    int i = i0 + warp;
    __shared__ float sE1[16][JC];
    __shared__ float sE2[16][JC];

    float T[16], s1[16], s2[16];
#pragma unroll
    for (int rh = 0; rh < 16; rh++) {
        int r = rh >> 2, h = rh & 3;
        T[rh] = g_T[LIDX(r, b, h, i)];
        s1[rh] = 0.f; s2[rh] = 0.f;
    }

    for (int jc = 0; jc < NN; jc += JC) {
        __syncthreads();
        for (int idx = threadIdx.x; idx < 16 * JC; idx += 256) {
            int rh = idx / JC, jj = idx % JC;
            int r = rh >> 2, h = rh & 3;
            int g = LIDX(r, b, h, jc + jj);
            sE1[rh][jj] = g_E1[g];
            sE2[rh][jj] = g_E2[g];
        }
        __syncthreads();
        for (int js = 0; js < JC; js += 32) {
            int j = jc + js + lane;
            const int4 av = *(const int4*)(adj + ((size_t)(b * NN + i) * NN + j) * RR);
            bool m0b = av.x != 0, m1b = av.y != 0, m2b = av.z != 0, m3b = av.w != 0;
            unsigned mr0 = __ballot_sync(~0u, m0b);
            unsigned mr1 = __ballot_sync(~0u, m1b);
            unsigned mr2 = __ballot_sync(~0u, m2b);
            unsigned mr3 = __ballot_sync(~0u, m3b);
            if (lane < 4) {
                unsigned w = (lane == 0) ? mr0 : (lane == 1) ? mr1 : (lane == 2) ? mr2 : mr3;
                g_mask[(((size_t)b * NN + i) * RR + lane) * (NN / 32) + ((jc + js) >> 5)] = w;
            }
            bool mm[4] = {m0b, m1b, m2b, m3b};
#pragma unroll
            for (int rh = 0; rh < 16; rh++) {
                if (mm[rh >> 2]) {
                    float e1 = sE1[rh][js + lane];
                    float e2 = sE2[rh][js + lane];
                    if (e1 > T[rh]) s1[rh] += e1; else s2[rh] += e2;
                }
            }
        }
    }
#pragma unroll
    for (int rh = 0; rh < 16; rh++) {
#pragma unroll
        for (int o = 16; o > 0; o >>= 1) {
            s1[rh] += __shfl_xor_sync(~0u, s1[rh], o);
            s2[rh] += __shfl_xor_sync(~0u, s2[rh], o);
        }
    }
#pragma unroll
    for (int rh = 0; rh < 16; rh++) {
        if (lane == rh) {
            int r = rh >> 2, h = rh & 3;
            int idx = LIDX(r, b, h, i);
            float A1 = g_A1p[idx], A2 = g_A2p[idx];
            float den = A1 * s1[rh] + A2 * s2[rh];
            if (!(den > 0.f)) { den = 1.f; A1 = 0.f; A2 = 0.f; }
            g_A1[idx] = A1 / den;
            g_A2[idx] = A2 / den;
        }
    }
}

// -------- kernel 4: out += P @ F with on-the-fly P (per (b, r, 32-row i-tile)) --------
__global__ __launch_bounds__(256) void k_pv(float* __restrict__ out) {
    int b = blockIdx.z, r = blockIdx.y, i0 = blockIdx.x * 32;
    int tid = threadIdx.x;
    int il = tid >> 3, cb = tid & 7;

    __shared__ float Fsh[16][256];
    __shared__ float Psh[16][128];
    __shared__ float sT[4][32], sA1[4][32], sA2[4][32];   // [h][i]
    __shared__ float sE1t[16][4], sE2t[16][4];            // [j][h]
    __shared__ unsigned smask[32];

    if (tid < 128) {
        int h = tid >> 5, ii = tid & 31;
        sT[h][ii]  = g_T [LIDX(r, b, h, i0 + ii)];
        sA1[h][ii] = g_A1[LIDX(r, b, h, i0 + ii)];
        sA2[h][ii] = g_A2[LIDX(r, b, h, i0 + ii)];
    }

    float4 acc[8];
#pragma unroll
    for (int k = 0; k < 8; k++) acc[k] = make_float4(0.f, 0.f, 0.f, 0.f);

    const float* Fbase = g_F + (size_t)(r * B + b) * NN * COUT;

    for (int jt = 0; jt < NN; jt += 16) {
        __syncthreads();
#pragma unroll
        for (int u = 0; u < 4; u++) {
            int idx = tid + u * 256;          // float4 index 0..1023
            int row = idx >> 6, c4 = idx & 63;
            *(float4*)&Fsh[row][c4 * 4] =
                *(const float4*)(Fbase + (size_t)(jt + row) * COUT + c4 * 4);
        }
        if (tid < 64) {
            int j = tid >> 2, h = tid & 3;
            sE1t[j][h] = g_E1[LIDX(r, b, h, jt + j)];
            sE2t[j][h] = g_E2[LIDX(r, b, h, jt + j)];
        }
        if (tid < 32) {
            smask[tid] = g_mask[(((size_t)b * NN + i0 + tid) * RR + r) * (NN / 32) + (jt >> 5)];
        }
        __syncthreads();

        int shift = jt & 16;
#pragma unroll
        for (int u = 0; u < 8; u++) {
            int e = tid + u * 256;            // 0..2047 : j*128 + ii*4 + h
            int h = e & 3, ii = (e >> 2) & 31, j = e >> 7;
            unsigned mbit = (smask[ii] >> (shift + j)) & 1u;
            float p = 0.f;
            if (mbit) {
                float e1 = sE1t[j][h];
                p = (e1 > sT[h][ii]) ? sA1[h][ii] * e1 : sA2[h][ii] * sE2t[j][h];
            }
            Psh[j][ii * 4 + h] = p;
        }
        __syncthreads();

#pragma unroll
        for (int j = 0; j < 16; j++) {
            float4 p4 = *(float4*)&Psh[j][il * 4];
            float pv[4] = {p4.x, p4.y, p4.z, p4.w};
#pragma unroll
            for (int k = 0; k < 8; k++) {
                int s = cb + 8 * k;           // h = k>>1 (compile-time)
                float4 f4 = *(float4*)&Fsh[j][s * 4];
                float p = pv[k >> 1];
                acc[k].x = fmaf(p, f4.x, acc[k].x);
                acc[k].y = fmaf(p, f4.y, acc[k].y);
                acc[k].z = fmaf(p, f4.z, acc[k].z);
                acc[k].w = fmaf(p, f4.w, acc[k].w);
            }
        }
    }

    float* op = out + (size_t)(b * NN + i0 + il) * COUT;
#pragma unroll
    for (int k = 0; k < 8; k++) {
        int s = cb + 8 * k;
        atomicAdd(&op[s * 4 + 0], acc[k].x);
        atomicAdd(&op[s * 4 + 1], acc[k].y);
        atomicAdd(&op[s * 4 + 2], acc[k].z);
        atomicAdd(&op[s * 4 + 3], acc[k].w);
    }
}

// -------- launch --------
extern "C" void kernel_launch(void* const* d_in, const int* in_sizes, int n_in,
                              void* d_out, int out_size) {
    const float* X   = (const float*)d_in[0];
    const int*   adj = (const int*)d_in[1];
    const float* W   = (const float*)d_in[2];
    const float* a   = (const float*)d_in[3];
    float* out = (float*)d_out;

    k_zero<<<(out_size + 255) / 256, 256>>>(out, out_size);
    k_gemm<<<dim3(COUT / 128, (B * NN) / 128, RR), 256>>>(X, W);
    k_lvec<<<(RR * B * NN) / 8, 256>>>(a);
    k_passA<<<dim3(NN / 8, B), 256>>>(adj);
    k_pv<<<dim3(NN / 32, RR, B), 256>>>(out);
}

// round 3
// speedup vs baseline: 1.7908x; 1.7908x over previous
#include <cuda_runtime.h>
#include <math.h>

#define B    8
#define NN   1024
#define CIN  256
#define COUT 256
#define RR   4
#define HH   4
#define ALPHA 0.2f

// -------- scratch (static __device__, per allocation rules) --------
__device__ float g_F[(size_t)RR * B * NN * COUT];         // [(r*B+b)*N+n][256]
__device__ float g_E1 [RR * B * HH * NN];   // exp(lj)
__device__ float g_E2 [RR * B * HH * NN];   // exp(0.2*lj)
__device__ float g_T  [RR * B * HH * NN];   // exp(-li)
__device__ float g_A1p[RR * B * HH * NN];   // exp(li)
__device__ float g_A2p[RR * B * HH * NN];   // exp(0.2*li)
__device__ float g_A1 [RR * B * HH * NN];   // exp(li)/den
__device__ float g_A2 [RR * B * HH * NN];   // exp(0.2*li)/den
__device__ unsigned g_mask[B * NN * RR * (NN / 32)];      // [((b*N+i)*R+r)*32 + j/32]

#define LIDX(r, b, h, n) ((((r) * B + (b)) * HH + (h)) * NN + (n))

// -------- kernel 0: zero output --------
__global__ void k_zero(float* __restrict__ out, int nel) {
    int i = blockIdx.x * 256 + threadIdx.x;
    if (i < nel) out[i] = 0.f;
}

// -------- kernel 1: F_r = X @ W[r]  (128x128 tile, 8x8 per-thread) --------
__global__ __launch_bounds__(256) void k_gemm(const float* __restrict__ X,
                                              const float* __restrict__ W) {
    int r  = blockIdx.z;
    int m0 = blockIdx.y * 128;
    int d0 = blockIdx.x * 128;
    __shared__ float As[8][128];
    __shared__ float Bs[8][128];
    const float* Wr = W + (size_t)r * CIN * COUT;
    float acc[8][8];
#pragma unroll
    for (int i = 0; i < 8; i++)
#pragma unroll
        for (int j = 0; j < 8; j++) acc[i][j] = 0.f;

    int tid = threadIdx.x;
    int tx = tid & 15, ty = tid >> 4;

    for (int k0 = 0; k0 < CIN; k0 += 8) {
        {
            int row = tid >> 1;
            int kq  = (tid & 1) * 4;
            float4 va = *(const float4*)(X + (size_t)(m0 + row) * CIN + k0 + kq);
            As[kq + 0][row] = va.x; As[kq + 1][row] = va.y;
            As[kq + 2][row] = va.z; As[kq + 3][row] = va.w;
        }
        {
            int krow = tid >> 5;
            int dq   = (tid & 31) * 4;
            *(float4*)&Bs[krow][dq] =
                *(const float4*)(Wr + (size_t)(k0 + krow) * COUT + d0 + dq);
        }
        __syncthreads();
#pragma unroll
        for (int kk = 0; kk < 8; kk++) {
            float av[8], bv[8];
            *(float4*)&av[0] = *(float4*)&As[kk][ty * 8];
            *(float4*)&av[4] = *(float4*)&As[kk][ty * 8 + 4];
            *(float4*)&bv[0] = *(float4*)&Bs[kk][tx * 8];
            *(float4*)&bv[4] = *(float4*)&Bs[kk][tx * 8 + 4];
#pragma unroll
            for (int i = 0; i < 8; i++)
#pragma unroll
                for (int j = 0; j < 8; j++)
                    acc[i][j] = fmaf(av[i], bv[j], acc[i][j]);
        }
        __syncthreads();
    }
    float* Fo = g_F + (size_t)r * (B * NN) * COUT;
#pragma unroll
    for (int i = 0; i < 8; i++) {
        int m = m0 + ty * 8 + i;
#pragma unroll
        for (int jq = 0; jq < 8; jq += 4) {
            float4 v = make_float4(acc[i][jq], acc[i][jq + 1], acc[i][jq + 2], acc[i][jq + 3]);
            *(float4*)(Fo + (size_t)m * COUT + d0 + tx * 8 + jq) = v;
        }
    }
}

// -------- kernel 2: li/lj dots + exp factor tables --------
__global__ __launch_bounds__(256) void k_lvec(const float* __restrict__ a) {
    int warp = threadIdx.x >> 5, lane = threadIdx.x & 31;
    int rbn = blockIdx.x * 8 + warp;           // 0 .. R*B*N-1
    int r = rbn >> 13;
    int bn = rbn & 8191;
    int b = bn >> 10, n = bn & 1023;
    const float* f = g_F + (size_t)rbn * COUT;
#pragma unroll
    for (int h = 0; h < HH; h++) {
        const float* ah = a + (r * HH + h) * 128;
        float f1 = f[h * 64 + lane];
        float f2 = f[h * 64 + 32 + lane];
        float li = f1 * ah[lane]      + f2 * ah[32 + lane];
        float lj = f1 * ah[64 + lane] + f2 * ah[96 + lane];
#pragma unroll
        for (int o = 16; o > 0; o >>= 1) {
            li += __shfl_xor_sync(~0u, li, o);
            lj += __shfl_xor_sync(~0u, lj, o);
        }
        if (lane == 0) {
            int idx = LIDX(r, b, h, n);
            g_E1[idx]  = expf(lj);
            g_E2[idx]  = expf(ALPHA * lj);
            g_T[idx]   = expf(-li);
            g_A1p[idx] = expf(li);
            g_A2p[idx] = expf(ALPHA * li);
        }
    }
}

// -------- kernel 3a: pure-streaming adjacency bit-pack --------
// one warp per (b, i, 32-j window); one int4 load per thread; max MLP via parallelism
__global__ __launch_bounds__(256) void k_pack(const int* __restrict__ adj) {
    int w    = (blockIdx.x * 256 + threadIdx.x) >> 5;
    int lane = threadIdx.x & 31;
    int jw = w & 31;
    int i  = (w >> 5) & 1023;
    int b  = w >> 15;
    int j  = jw * 32 + lane;
    const int4 av = *(const int4*)(adj + ((size_t)(b * NN + i) * NN + j) * RR);
    unsigned m0 = __ballot_sync(~0u, av.x != 0);
    unsigned m1 = __ballot_sync(~0u, av.y != 0);
    unsigned m2 = __ballot_sync(~0u, av.z != 0);
    unsigned m3 = __ballot_sync(~0u, av.w != 0);
    if (lane < 4) {
        unsigned mv = (lane == 0) ? m0 : (lane == 1) ? m1 : (lane == 2) ? m2 : m3;
        g_mask[(((size_t)b * NN + i) * RR + lane) * (NN / 32) + jw] = mv;
    }
}

// -------- kernel 3b: softmax denominators from packed bits --------
#define JC 256
__global__ __launch_bounds__(256) void k_denom() {
    int b  = blockIdx.y;
    int i0 = blockIdx.x * 8;
    int warp = threadIdx.x >> 5, lane = threadIdx.x & 31;
    int i = i0 + warp;
    int bn = b * NN + i;
    __shared__ float sE1[16][JC];
    __shared__ float sE2[16][JC];

    float T[16], s1[16], s2[16];
#pragma unroll
    for (int rh = 0; rh < 16; rh++) {
        int r = rh >> 2, h = rh & 3;
        T[rh] = g_T[LIDX(r, b, h, i)];
        s1[rh] = 0.f; s2[rh] = 0.f;
    }

    for (int jc = 0; jc < NN; jc += JC) {
        __syncthreads();
        for (int idx = threadIdx.x; idx < 16 * JC; idx += 256) {
            int rh = idx / JC, jj = idx % JC;
            int r = rh >> 2, h = rh & 3;
            int g = LIDX(r, b, h, jc + jj);
            sE1[rh][jj] = g_E1[g];
            sE2[rh][jj] = g_E2[g];
        }
        __syncthreads();
        for (int js = 0; js < JC; js += 32) {
            int jword = (jc + js) >> 5;
            unsigned mw[4];
#pragma unroll
            for (int r = 0; r < 4; r++)
                mw[r] = g_mask[(((size_t)bn) * RR + r) * (NN / 32) + jword];
#pragma unroll
            for (int rh = 0; rh < 16; rh++) {
                if ((mw[rh >> 2] >> lane) & 1u) {
                    float e1 = sE1[rh][js + lane];
                    float e2 = sE2[rh][js + lane];
                    if (e1 > T[rh]) s1[rh] += e1; else s2[rh] += e2;
                }
            }
        }
    }
#pragma unroll
    for (int rh = 0; rh < 16; rh++) {
#pragma unroll
        for (int o = 16; o > 0; o >>= 1) {
            s1[rh] += __shfl_xor_sync(~0u, s1[rh], o);
            s2[rh] += __shfl_xor_sync(~0u, s2[rh], o);
        }
    }
#pragma unroll
    for (int rh = 0; rh < 16; rh++) {
        if (lane == rh) {
            int r = rh >> 2, h = rh & 3;
            int idx = LIDX(r, b, h, i);
            float A1 = g_A1p[idx], A2 = g_A2p[idx];
            float den = A1 * s1[rh] + A2 * s2[rh];
            if (!(den > 0.f)) { den = 1.f; A1 = 0.f; A2 = 0.f; }
            g_A1[idx] = A1 / den;
            g_A2[idx] = A2 / den;
        }
    }
}

// -------- kernel 4: out += P @ F, 64-row i-tile, 8x8 register blocking --------
// thread (iq, cg): rows i0+iq*8..+8, cols {cg*4..+3, 128+cg*4..+3}
__global__ __launch_bounds__(256, 2) void k_pv(float* __restrict__ out) {
    int b = blockIdx.z, r = blockIdx.y, i0 = blockIdx.x * 64;
    int tid = threadIdx.x;
    int cg = tid & 31;
    int iq = tid >> 5;
    int h0 = cg >> 4;        // 0 or 1 (cols cg*4 in [0,128))
    int h1 = h0 + 2;         // cols 128+cg*4 in [128,256)

    __shared__ float Fsh[16][256];        // 16 KB
    __shared__ float Psh[16][4][64];      // 16 KB  [j][h][i]
    __shared__ float sT[4][64], sA1[4][64], sA2[4][64];
    __shared__ float sE1t[16][4], sE2t[16][4];
    __shared__ unsigned smask[64];

    {   // per-i tables: 4h x 64i = 256 entries
        int h = tid >> 6, ii = tid & 63;
        int g = LIDX(r, b, h, i0 + ii);
        sT[h][ii]  = g_T[g];
        sA1[h][ii] = g_A1[g];
        sA2[h][ii] = g_A2[g];
    }

    float4 accA[8], accB[8];
#pragma unroll
    for (int k = 0; k < 8; k++) {
        accA[k] = make_float4(0.f, 0.f, 0.f, 0.f);
        accB[k] = make_float4(0.f, 0.f, 0.f, 0.f);
    }

    const float* Fbase = g_F + (size_t)(r * B + b) * NN * COUT;

    for (int jt = 0; jt < NN; jt += 16) {
        __syncthreads();
#pragma unroll
        for (int u = 0; u < 4; u++) {
            int idx = tid + u * 256;
            int row = idx >> 6, c4 = idx & 63;
            *(float4*)&Fsh[row][c4 * 4] =
                *(const float4*)(Fbase + (size_t)(jt + row) * COUT + c4 * 4);
        }
        if (tid < 64) {
            int j = tid >> 2, h = tid & 3;
            sE1t[j][h] = g_E1[LIDX(r, b, h, jt + j)];
            sE2t[j][h] = g_E2[LIDX(r, b, h, jt + j)];
        }
        if ((jt & 31) == 0 && tid < 64) {
            smask[tid] = g_mask[(((size_t)b * NN + i0 + tid) * RR + r) * (NN / 32) + (jt >> 5)];
        }
        __syncthreads();

        // build P[j][h][i] for this 16-j tile (4096 entries, 16/thread)
        int shift = jt & 16;
#pragma unroll
        for (int u = 0; u < 16; u++) {
            int e = tid + u * 256;
            int ii = e & 63, h = (e >> 6) & 3, j = e >> 8;
            unsigned bit = (smask[ii] >> (shift + j)) & 1u;
            float p = 0.f;
            if (bit) {
                float e1 = sE1t[j][h];
                p = (e1 > sT[h][ii]) ? sA1[h][ii] * e1 : sA2[h][ii] * sE2t[j][h];
            }
            Psh[j][h][ii] = p;
        }
        __syncthreads();

#pragma unroll
        for (int j = 0; j < 16; j++) {
            float4 f0 = *(float4*)&Fsh[j][cg * 4];
            float4 f1 = *(float4*)&Fsh[j][128 + cg * 4];
            float4 pa0 = *(float4*)&Psh[j][h0][iq * 8];
            float4 pa1 = *(float4*)&Psh[j][h0][iq * 8 + 4];
            float4 pb0 = *(float4*)&Psh[j][h1][iq * 8];
            float4 pb1 = *(float4*)&Psh[j][h1][iq * 8 + 4];
            float pa[8] = {pa0.x, pa0.y, pa0.z, pa0.w, pa1.x, pa1.y, pa1.z, pa1.w};
            float pb[8] = {pb0.x, pb0.y, pb0.z, pb0.w, pb1.x, pb1.y, pb1.z, pb1.w};
#pragma unroll
            for (int k = 0; k < 8; k++) {
                float p = pa[k];
                accA[k].x = fmaf(p, f0.x, accA[k].x);
                accA[k].y = fmaf(p, f0.y, accA[k].y);
                accA[k].z = fmaf(p, f0.z, accA[k].z);
                accA[k].w = fmaf(p, f0.w, accA[k].w);
                float q = pb[k];
                accB[k].x = fmaf(q, f1.x, accB[k].x);
                accB[k].y = fmaf(q, f1.y, accB[k].y);
                accB[k].z = fmaf(q, f1.z, accB[k].z);
                accB[k].w = fmaf(q, f1.w, accB[k].w);
            }
        }
    }

#pragma unroll
    for (int k = 0; k < 8; k++) {
        float* op = out + (size_t)(b * NN + i0 + iq * 8 + k) * COUT;
        atomicAdd(&op[cg * 4 + 0], accA[k].x);
        atomicAdd(&op[cg * 4 + 1], accA[k].y);
        atomicAdd(&op[cg * 4 + 2], accA[k].z);
        atomicAdd(&op[cg * 4 + 3], accA[k].w);
        atomicAdd(&op[128 + cg * 4 + 0], accB[k].x);
        atomicAdd(&op[128 + cg * 4 + 1], accB[k].y);
        atomicAdd(&op[128 + cg * 4 + 2], accB[k].z);
        atomicAdd(&op[128 + cg * 4 + 3], accB[k].w);
    }
}

// -------- launch --------
extern "C" void kernel_launch(void* const* d_in, const int* in_sizes, int n_in,
                              void* d_out, int out_size) {
    const float* X   = (const float*)d_in[0];
    const int*   adj = (const int*)d_in[1];
    const float* W   = (const float*)d_in[2];
    const float* a   = (const float*)d_in[3];
    float* out = (float*)d_out;

    k_zero<<<(out_size + 255) / 256, 256>>>(out, out_size);
    k_gemm<<<dim3(COUT / 128, (B * NN) / 128, RR), 256>>>(X, W);
    k_lvec<<<(RR * B * NN) / 8, 256>>>(a);
    k_pack<<<(B * NN * 32) / 8, 256>>>(adj);
    k_denom<<<dim3(NN / 8, B), 256>>>();
    k_pv<<<dim3(NN / 64, RR, B), 256>>>(out);
}